// round 1
// baseline (speedup 1.0000x reference)
#include <cuda_runtime.h>

// Sineconv: out[b,l,f] = sum_{w=0}^{64} x[b, l + 2f + ((f+w)>>5)] * sines[f, l+w]
//                        + x[b, l+32] * res_kernel[f]
// sines[f,s] = amplitude[f] * sin( ((frequency[f]*19000)*2pi) * sine_range[s] + phases[f]*2pi )
//
// The x factor is piecewise-constant in w over 3 ranges, so each output needs only
// 3 contiguous range-sums of sines (from an fp64 prefix scan) + residual.

#define S_TOTAL 16384
#define L_OUT   16320
#define F_N     32
#define B_N     4
#define TILE_L  64
#define NS      (TILE_L + 65)   // 129 sine samples per tile (with halo)
#define NPP     131             // padded prefix row (NS+1 = 130 entries, pad to 131)
#define XW      (TILE_L + 68)   // padded x stage width

// Accurate sinf replacement: fp64 quadrant reduction + fp32 minimax polys.
// Matches libdevice sinf (what XLA emits for jnp.sin) to ~1 ulp for |x| < ~1e6,
// regardless of --use_fast_math.
__device__ __forceinline__ float acc_sinf(float xf) {
    double a = (double)xf;
    double kd = rint(a * 0.63661977236758134308);           // 2/pi
    double r  = fma(-kd, 1.5707963267948966, a);            // |r| <= pi/4 (+~1e-12)
    int q = ((int)kd) & 3;
    float rf = (float)r;
    float r2 = rf * rf;
    // sin poly on [-pi/4, pi/4]
    float sp = fmaf(r2, fmaf(r2, fmaf(r2, -1.9841269841e-4f, 8.3333333333e-3f),
                             -1.6666666667e-1f), 1.0f);
    float s  = rf * sp;
    // cos poly on [-pi/4, pi/4]
    float c  = fmaf(r2, fmaf(r2, fmaf(r2, fmaf(r2, 2.4801587302e-5f, -1.3888888889e-3f),
                             4.1666666667e-2f), -5.0e-1f), 1.0f);
    float v = (q & 1) ? c : s;
    return (q & 2) ? -v : v;
}

__global__ __launch_bounds__(256) void sineconv_kernel(
    const float* __restrict__ x,          // (B, S, 1)
    const float* __restrict__ sr,         // (S,)
    const float* __restrict__ phases,     // (32,)
    const float* __restrict__ amplitude,  // (32,)
    const float* __restrict__ frequency,  // (32,)
    const float* __restrict__ res_kernel, // (32,)
    float* __restrict__ out)              // (B, L, F)
{
    __shared__ double Psh[F_N][NPP];   // exclusive prefix of sines per feature row
    __shared__ float  xsh[B_N][XW];

    const int tid  = threadIdx.x;
    const int lane = tid & 31;
    const int warp = tid >> 5;
    const int s0   = blockIdx.x * TILE_L;

    // ---- stage x halo: s in [s0, s0 + TILE_L + 66] ----
    for (int idx = tid; idx < B_N * (TILE_L + 67); idx += 256) {
        int b = idx / (TILE_L + 67);
        int i = idx - b * (TILE_L + 67);
        int s = s0 + i;
        xsh[b][i] = (s < S_TOTAL) ? x[b * S_TOTAL + s] : 0.0f;
    }

    // ---- sines + fp64 prefix scan: 8 warps, each owns 4 feature rows ----
    const float TWO_PI = 6.28318530717958647692f;
    for (int fr = warp; fr < F_N; fr += 8) {
        // Replicate reference fp32 rounding: ((freq*19000)*2pi)*sr + ph
        float fq  = __fmul_rn(frequency[fr], 19000.0f);
        float w2  = __fmul_rn(fq, TWO_PI);
        float ph  = __fmul_rn(phases[fr], TWO_PI);
        float amp = amplitude[fr];

        // lane handles 5 consecutive elements: local serial prefix
        double loc[5];
        double run = 0.0;
        int j0 = lane * 5;
#pragma unroll
        for (int k = 0; k < 5; k++) {
            int j = j0 + k;
            int s = s0 + j;
            double v = 0.0;
            if (j < NS && s < S_TOTAL) {
                float arg = __fadd_rn(__fmul_rn(w2, sr[s]), ph);
                v = (double)__fmul_rn(amp, acc_sinf(arg));
            }
            run += v;
            loc[k] = run;
        }
        // exclusive scan of lane totals across the warp
        double t = run;
#pragma unroll
        for (int off = 1; off < 32; off <<= 1) {
            double n = __shfl_up_sync(0xFFFFFFFFu, t, off);
            if (lane >= off) t += n;
        }
        double excl = t - run;
        if (lane == 0) Psh[fr][0] = 0.0;
#pragma unroll
        for (int k = 0; k < 5; k++) {
            int j = j0 + k;
            if (j < NS) Psh[fr][1 + j] = excl + loc[k];
        }
    }
    __syncthreads();

    // ---- epilogue: lanes along f (coalesced stores), 8 l-rows per thread ----
    const int f    = tid & 31;
    const int row0 = tid >> 5;
    const float rk = res_kernel[f];
    const int i32 = 32 - f;
    const int i64 = 64 - f;

#pragma unroll
    for (int it = 0; it < 8; it++) {
        int i = row0 + it * 8;           // local l index, 0..63
        int l = s0 + i;                  // grid is exact: l < L_OUT always
        double p0 = Psh[f][i];
        double pa = Psh[f][i + i32];
        double pb = Psh[f][i + i64];
        double p3 = Psh[f][i + 65];
        float A0 = (float)(pa - p0);     // sum sines[f, l .. l+31-f]
        float A1 = (float)(pb - pa);     // sum sines[f, l+32-f .. l+63-f]
        float A2 = (float)(p3 - pb);     // sum sines[f, l+64-f .. l+64]
        int xb = i + 2 * f;
#pragma unroll
        for (int b = 0; b < B_N; b++) {
            float r = fmaf(xsh[b][xb],     A0,
                      fmaf(xsh[b][xb + 1], A1,
                      fmaf(xsh[b][xb + 2], A2,
                           xsh[b][i + 32] * rk)));
            out[(b * L_OUT + l) * F_N + f] = r;
        }
    }
}

extern "C" void kernel_launch(void* const* d_in, const int* in_sizes, int n_in,
                              void* d_out, int out_size) {
    const float* x    = (const float*)d_in[0];
    const float* sr   = (const float*)d_in[1];
    const float* ph   = (const float*)d_in[2];
    const float* amp  = (const float*)d_in[3];
    const float* freq = (const float*)d_in[4];
    const float* rk   = (const float*)d_in[5];
    float* out = (float*)d_out;

    sineconv_kernel<<<L_OUT / TILE_L, 256>>>(x, sr, ph, amp, freq, rk, out);
}

// round 2
// speedup vs baseline: 3.6100x; 3.6100x over previous
#include <cuda_runtime.h>

// Sineconv: out[b,l,f] = sum_{w=0}^{64} x[b, l + 2f + ((f+w)>>5)] * sines[f, l+w]
//                        + x[b, l+32] * res_kernel[f]
// sines[f,s] = amplitude[f] * sin( ((frequency[f]*19000)*2pi) * sine_range[s] + phases[f]*2pi )
//
// x factor is piecewise-constant in w over 3 ranges -> each output needs only
// 3 contiguous range-sums of sines (from an fp32 prefix scan) + residual.
// NO fp64 anywhere: B300's FP64 pipe is near-dead (rt ~18.4 cyc/op).

#define S_TOTAL 16384
#define L_OUT   16320
#define F_N     32
#define B_N     4
#define TILE_L  64
#define NS      (TILE_L + 65)   // 129 sine samples per tile (with halo)
#define NPP     131             // prefix row: 130 entries, stride 131 (131%32=3 -> conflict-free)
#define XW      (TILE_L + 68)   // padded x stage width

// Accurate sinf via fp32 FMA Cody-Waite (exact internal products).
// |arg| <= ~1e5 here (k <= 2^17): total reduction error ~6e-8 rad.
__device__ __forceinline__ float acc_sinf(float a) {
    float kf = rintf(a * 0.63661977236758134f);          // 2/pi; fp32 err << 0.5
    float r  = fmaf(-kf, 1.57079637050628662e+0f, a);    // c1 = float(pi/2)
    r        = fmaf(-kf, -4.37113900018624283e-8f, r);   // c2 = float(pi/2 - c1)
    int   q  = (int)kf;                                  // &3 gives true mod 4 (two's comp)
    float r2 = r * r;
    float sp = fmaf(r2, fmaf(r2, fmaf(r2, -1.9841269841e-4f, 8.3333333333e-3f),
                             -1.6666666667e-1f), 1.0f);
    float s  = r * sp;
    float c  = fmaf(r2, fmaf(r2, fmaf(r2, fmaf(r2, 2.4801587302e-5f, -1.3888888889e-3f),
                             4.1666666667e-2f), -5.0e-1f), 1.0f);
    float v = (q & 1) ? c : s;
    return (q & 2) ? -v : v;
}

__global__ __launch_bounds__(256) void sineconv_kernel(
    const float* __restrict__ x,          // (B, S, 1)
    const float* __restrict__ sr,         // (S,)
    const float* __restrict__ phases,     // (32,)
    const float* __restrict__ amplitude,  // (32,)
    const float* __restrict__ frequency,  // (32,)
    const float* __restrict__ res_kernel, // (32,)
    float* __restrict__ out)              // (B, L, F)
{
    __shared__ float Psh[F_N][NPP];    // exclusive prefix of sines per feature row
    __shared__ float xsh[B_N][XW];
    __shared__ float srsh[NS];

    const int tid  = threadIdx.x;
    const int lane = tid & 31;
    const int warp = tid >> 5;
    const int s0   = blockIdx.x * TILE_L;

    // ---- stage x halo (s in [s0, s0+130]) and sr tile ----
    for (int idx = tid; idx < B_N * (TILE_L + 67); idx += 256) {
        int b = idx / (TILE_L + 67);
        int i = idx - b * (TILE_L + 67);
        int s = s0 + i;
        xsh[b][i] = (s < S_TOTAL) ? x[b * S_TOTAL + s] : 0.0f;
    }
    if (tid < NS) {
        int s = s0 + tid;
        srsh[tid] = (s < S_TOTAL) ? sr[s] : 0.0f;
    }
    __syncthreads();

    // ---- sines + fp32 prefix scan: 8 warps, each owns 4 feature rows ----
    const float TWO_PI = 6.28318530717958647692f;
    for (int fr = warp; fr < F_N; fr += 8) {
        // Replicate reference fp32 rounding: ((freq*19000)*2pi)*sr + ph
        float w2  = __fmul_rn(__fmul_rn(frequency[fr], 19000.0f), TWO_PI);
        float ph  = __fmul_rn(phases[fr], TWO_PI);
        float amp = amplitude[fr];

        // lane handles 5 consecutive elements: local serial prefix
        float loc[5];
        float run = 0.0f;
        int j0 = lane * 5;
#pragma unroll
        for (int k = 0; k < 5; k++) {
            int j = j0 + k;
            float v = 0.0f;
            if (j < NS && (s0 + j) < S_TOTAL) {
                float arg = __fadd_rn(__fmul_rn(w2, srsh[j]), ph);
                v = __fmul_rn(amp, acc_sinf(arg));
            }
            run += v;
            loc[k] = run;
        }
        // exclusive scan of lane totals across the warp
        float t = run;
#pragma unroll
        for (int off = 1; off < 32; off <<= 1) {
            float n = __shfl_up_sync(0xFFFFFFFFu, t, off);
            if (lane >= off) t += n;
        }
        float excl = t - run;
        if (lane == 0) Psh[fr][0] = 0.0f;
#pragma unroll
        for (int k = 0; k < 5; k++) {
            int j = j0 + k;
            if (j < NS) Psh[fr][1 + j] = excl + loc[k];
        }
    }
    __syncthreads();

    // ---- epilogue: lanes along f (coalesced 128B stores), 8 l-rows/thread ----
    const int f    = tid & 31;
    const int row0 = tid >> 5;
    const float rk = res_kernel[f];
    const int i32 = 32 - f;
    const int i64 = 64 - f;

#pragma unroll
    for (int it = 0; it < 8; it++) {
        int i = row0 + it * 8;           // local l index, 0..63
        int l = s0 + i;                  // grid exact: l < L_OUT always
        float p0 = Psh[f][i];
        float pa = Psh[f][i + i32];
        float pb = Psh[f][i + i64];
        float p3 = Psh[f][i + 65];
        float A0 = pa - p0;              // sum sines[f, l .. l+31-f]
        float A1 = pb - pa;              // sum sines[f, l+32-f .. l+63-f]
        float A2 = p3 - pb;              // sum sines[f, l+64-f .. l+64]
        int xb = i + 2 * f;
#pragma unroll
        for (int b = 0; b < B_N; b++) {
            float r = fmaf(xsh[b][xb],     A0,
                      fmaf(xsh[b][xb + 1], A1,
                      fmaf(xsh[b][xb + 2], A2,
                           xsh[b][i + 32] * rk)));
            out[(b * L_OUT + l) * F_N + f] = r;
        }
    }
}

extern "C" void kernel_launch(void* const* d_in, const int* in_sizes, int n_in,
                              void* d_out, int out_size) {
    const float* x    = (const float*)d_in[0];
    const float* sr   = (const float*)d_in[1];
    const float* ph   = (const float*)d_in[2];
    const float* amp  = (const float*)d_in[3];
    const float* freq = (const float*)d_in[4];
    const float* rk   = (const float*)d_in[5];
    float* out = (float*)d_out;

    sineconv_kernel<<<L_OUT / TILE_L, 256>>>(x, sr, ph, amp, freq, rk, out);
}

// round 4
// speedup vs baseline: 3.7784x; 1.0466x over previous
#include <cuda_runtime.h>

// Sineconv: out[b,l,f] = sum_{w=0}^{64} x[b, l + 2f + ((f+w)>>5)] * sines[f, l+w]
//                        + x[b, l+32] * res_kernel[f]
// sines[f,s] = amplitude[f] * sin( ((frequency[f]*19000)*2pi) * sine_range[s] + phases[f]*2pi )
//
// x factor is piecewise-constant in w over 3 ranges -> each output needs only
// 3 contiguous range-sums of sines (fp32 prefix scan) + residual.
//
// Block = (l-tile of 64, f-group of 8): 1020 CTAs, one sine row per warp.
// R3 fix: each lane owns exactly 4 scan samples (j=4*lane+k, covers 0..127);
// sample j=128 appended post-scan by lane 31 only. (R2's overlapping 5th
// sample double-counted into the scan and raced on Psh writes.)

#define S_TOTAL 16384
#define L_OUT   16320
#define F_N     32
#define B_N     4
#define TILE_L  64
#define FG      8               // features per block
#define NS      (TILE_L + 65)   // 129 sine samples per tile (with halo)
#define NPP     132             // prefix row stride; 132%32==4 -> (fl*4+i) perfect bank perm
#define XW      (TILE_L + 68)   // padded x stage width

// Accurate sinf via fp32 FMA Cody-Waite (exact internal products).
// |arg| <= ~1e5 here: total reduction error ~6e-8 rad.
__device__ __forceinline__ float acc_sinf(float a) {
    float kf = rintf(a * 0.63661977236758134f);          // 2/pi
    float r  = fmaf(-kf, 1.57079637050628662e+0f, a);    // c1 = float(pi/2)
    r        = fmaf(-kf, -4.37113900018624283e-8f, r);   // c2 = float(pi/2 - c1)
    int   q  = (int)kf;
    float r2 = r * r;
    float sp = fmaf(r2, fmaf(r2, fmaf(r2, -1.9841269841e-4f, 8.3333333333e-3f),
                             -1.6666666667e-1f), 1.0f);
    float s  = r * sp;
    float c  = fmaf(r2, fmaf(r2, fmaf(r2, fmaf(r2, 2.4801587302e-5f, -1.3888888889e-3f),
                             4.1666666667e-2f), -5.0e-1f), 1.0f);
    float v = (q & 1) ? c : s;
    return (q & 2) ? -v : v;
}

__global__ __launch_bounds__(256) void sineconv_kernel(
    const float* __restrict__ x,          // (B, S, 1)
    const float* __restrict__ sr,         // (S,)
    const float* __restrict__ phases,     // (32,)
    const float* __restrict__ amplitude,  // (32,)
    const float* __restrict__ frequency,  // (32,)
    const float* __restrict__ res_kernel, // (32,)
    float* __restrict__ out)              // (B, L, F)
{
    __shared__ float Psh[FG][NPP];     // exclusive prefix of sines, this block's 8 rows
    __shared__ float xsh[B_N][XW];
    __shared__ float srsh[NS];

    const int tid  = threadIdx.x;
    const int lane = tid & 31;
    const int warp = tid >> 5;
    const int s0   = blockIdx.x * TILE_L;
    const int fg0  = blockIdx.y * FG;

    // ---- stage x halo (s in [s0, s0+130]) and sr tile ----
    for (int idx = tid; idx < B_N * (TILE_L + 67); idx += 256) {
        int b = idx / (TILE_L + 67);
        int i = idx - b * (TILE_L + 67);
        int s = s0 + i;
        xsh[b][i] = (s < S_TOTAL) ? x[b * S_TOTAL + s] : 0.0f;
    }
    if (tid < NS) {
        int s = s0 + tid;
        srsh[tid] = (s < S_TOTAL) ? sr[s] : 0.0f;
    }
    __syncthreads();

    // ---- sines + fp32 prefix scan: each of 8 warps owns ONE feature row ----
    {
        const float TWO_PI = 6.28318530717958647692f;
        const int f = fg0 + warp;
        // Replicate reference fp32 rounding: ((freq*19000)*2pi)*sr + ph
        float w2  = __fmul_rn(__fmul_rn(frequency[f], 19000.0f), TWO_PI);
        float ph  = __fmul_rn(phases[f], TWO_PI);
        float amp = amplitude[f];

        // each lane owns exactly 4 consecutive samples: j = 4*lane + k (0..127)
        float loc[4];
        float run = 0.0f;
        int j0 = lane * 4;
#pragma unroll
        for (int k = 0; k < 4; k++) {
            int j = j0 + k;
            float v = 0.0f;
            if ((s0 + j) < S_TOTAL) {
                float arg = __fadd_rn(__fmul_rn(w2, srsh[j]), ph);
                v = __fmul_rn(amp, acc_sinf(arg));
            }
            run += v;
            loc[k] = run;
        }
        // exclusive scan of lane totals across the warp
        float t = run;
#pragma unroll
        for (int off = 1; off < 32; off <<= 1) {
            float n = __shfl_up_sync(0xFFFFFFFFu, t, off);
            if (lane >= off) t += n;
        }
        float excl = t - run;
        if (lane == 0) Psh[warp][0] = 0.0f;
#pragma unroll
        for (int k = 0; k < 4; k++) {
            Psh[warp][1 + j0 + k] = excl + loc[k];
        }
        // final sample j = 128: appended by lane 31 only (inclusive through 128)
        if (lane == 31) {
            float v = 0.0f;
            if ((s0 + 128) < S_TOTAL) {
                float arg = __fadd_rn(__fmul_rn(w2, srsh[128]), ph);
                v = __fmul_rn(amp, acc_sinf(arg));
            }
            Psh[warp][1 + 128] = (excl + loc[3]) + v;
        }
    }
    __syncthreads();

    // ---- epilogue: thread -> (fl = tid&7, i = tid>>3), 2 l-passes x 4 batches ----
    const int fl = tid & 7;
    const int f  = fg0 + fl;
    const int i0 = tid >> 3;             // 0..31
    const float rk = res_kernel[f];
    const int i32 = 32 - f;
    const int i64 = 64 - f;

#pragma unroll
    for (int p = 0; p < 2; p++) {
        int i = i0 + p * 32;             // local l index, 0..63
        int l = s0 + i;                  // grid exact: l < L_OUT always
        float p0 = Psh[fl][i];
        float pa = Psh[fl][i + i32];
        float pb = Psh[fl][i + i64];
        float p3 = Psh[fl][i + 65];
        float A0 = pa - p0;              // sum sines[f, l .. l+31-f]
        float A1 = pb - pa;              // sum sines[f, l+32-f .. l+63-f]
        float A2 = p3 - pb;              // sum sines[f, l+64-f .. l+64]
        int xb = i + 2 * f;
#pragma unroll
        for (int b = 0; b < B_N; b++) {
            float r = fmaf(xsh[b][xb],     A0,
                      fmaf(xsh[b][xb + 1], A1,
                      fmaf(xsh[b][xb + 2], A2,
                           xsh[b][i + 32] * rk)));
            out[(b * L_OUT + l) * F_N + f] = r;
        }
    }
}

extern "C" void kernel_launch(void* const* d_in, const int* in_sizes, int n_in,
                              void* d_out, int out_size) {
    const float* x    = (const float*)d_in[0];
    const float* sr   = (const float*)d_in[1];
    const float* ph   = (const float*)d_in[2];
    const float* amp  = (const float*)d_in[3];
    const float* freq = (const float*)d_in[4];
    const float* rk   = (const float*)d_in[5];
    float* out = (float*)d_out;

    dim3 grid(L_OUT / TILE_L, F_N / FG);
    sineconv_kernel<<<grid, 256>>>(x, sr, ph, amp, freq, rk, out);
}